// round 1
// baseline (speedup 1.0000x reference)
#include <cuda_runtime.h>
#include <cuda_bf16.h>
#include <math.h>

// ---------------- constants ----------------
#define PATCH   7
#define HALF    3
#define NTAPS   49      // PATCH*PATCH
#define CENTER  24      // 3*7+3
#define KNN     5
#define MAXPTS  65536
#define MAXB    64

// ---------------- device scratch (no allocations allowed) ----------------
__device__ float g_x[MAXPTS];     // pm x (valid) else 0
__device__ float g_z[MAXPTS];     // pm z (valid) else 0
__device__ float g_h[MAXPTS];     // pm y (height), always stored
__device__ float g_sq[MAXPTS];    // x*x+z*z (valid) else 4e18 poison
__device__ unsigned char g_valid[MAXPTS];

__device__ int   g_validn[MAXB];  // n_valid per batch
__device__ float g_Sh[MAXB];      // sum h*vf per batch
__device__ float g_Sls[MAXB];     // sum smooth_l1(h, local_mean, .01)*vf per batch
__device__ float g_Ssl[MAXB];     // sum slope penalties per batch

// global scalar accumulators:
// [0]=sum(scores) [1]=sum(ydiff*scores) [2]=sum(ydiff)
// [3]=sum(w)      [4]=sum(diff*w)       [5]=sum(sl1(cl,cr,1)*w)
__device__ float g_acc[8];
__device__ int   g_cnt;          // count(scores > 0.1)

// ---------------- helpers ----------------
__device__ __forceinline__ float smooth_l1f(float x, float y, float beta) {
    float d = fabsf(x - y);
    return d < beta ? 0.5f * d * d / beta : d - 0.5f * beta;
}

__device__ __forceinline__ float bilinear(const float* __restrict__ im,
                                          float x, float y, int W, int H) {
    x = fminf(fmaxf(x, 0.f), (float)(W - 1));
    y = fminf(fmaxf(y, 0.f), (float)(H - 1));
    float x0 = floorf(x), y0 = floorf(y);
    float fx = x - x0, fy = y - y0;
    int x0i = min(max((int)x0, 0), W - 1);
    int x1i = min(x0i + 1, W - 1);
    int y0i = min(max((int)y0, 0), H - 1);
    int y1i = min(y0i + 1, H - 1);
    float v00 = __ldg(im + (size_t)y0i * W + x0i);
    float v01 = __ldg(im + (size_t)y0i * W + x1i);
    float v10 = __ldg(im + (size_t)y1i * W + x0i);
    float v11 = __ldg(im + (size_t)y1i * W + x1i);
    float top = v00 * (1.f - fx) + v01 * fx;
    float bot = v10 * (1.f - fx) + v11 * fx;
    return top * (1.f - fy) + bot * fy;
}

// ---------------- kernel 0: zero accumulators ----------------
__global__ void zero_kernel() {
    int t = threadIdx.x;
    if (t < 8)   g_acc[t] = 0.f;
    if (t == 8)  g_cnt = 0;
    if (t < MAXB) {
        g_validn[t] = 0;
        g_Sh[t] = 0.f;
        g_Sls[t] = 0.f;
        g_Ssl[t] = 0.f;
    }
}

// ---------------- kernel 1: per-point photo + geometry ----------------
// one warp per keypoint; 8 warps / block
__global__ void point_kernel(const float* __restrict__ lg,
                             const float* __restrict__ rg,
                             const float* __restrict__ kpl,
                             const float* __restrict__ kpr,
                             const float* __restrict__ scores,
                             const float* __restrict__ Q,
                             int B, int N, int H, int W) {
    __shared__ float sacc[6];
    __shared__ int   scnt;
    int tid  = threadIdx.x;
    int warp = tid >> 5;
    int lane = tid & 31;
    if (tid < 6) sacc[tid] = 0.f;
    if (tid == 6) scnt = 0;
    __syncthreads();

    int total = B * N;
    int p = blockIdx.x * 8 + warp;
    if (p < total) {
        int b = p / N;
        float klx = kpl[2 * p],     kly = kpl[2 * p + 1];
        float krx = kpr[2 * p],     kry = kpr[2 * p + 1];
        float sc  = scores[p];

        // geometry: proj[j] = sum_i pts4[i] * Q[b,j,i], pts4 = [klx, kly, disp, 1]
        const float* Qb = Q + (size_t)b * 16;
        float disp = klx - krx;
        float p0 = Qb[0]  * klx + Qb[1]  * kly + Qb[2]  * disp + Qb[3];
        float p1 = Qb[4]  * klx + Qb[5]  * kly + Qb[6]  * disp + Qb[7];
        float p2 = Qb[8]  * klx + Qb[9]  * kly + Qb[10] * disp + Qb[11];
        float p3 = Qb[12] * klx + Qb[13] * kly + Qb[14] * disp + Qb[15];
        float Wc  = fmaxf(p3, 1e-6f);
        float X = p0 / Wc, Y = p1 / Wc, Z = p2 / Wc;
        bool  valid = (Z > 100.f) && (Z < 30000.f) && (sc > 0.1f);
        float pmx = X / 1000.f;
        float hh  = Y / 1000.f;
        float pmz = Z / 1000.f;
        float sq  = pmx * pmx + pmz * pmz;

        if (lane == 0) {
            g_h[p]     = hh;
            g_valid[p] = valid ? 1 : 0;
            if (valid) { g_x[p] = pmx; g_z[p] = pmz; g_sq[p] = sq; }
            else       { g_x[p] = 0.f; g_z[p] = 0.f; g_sq[p] = 4e18f; }
        }

        // patch sampling: taps strided over lanes
        const float* L = lg + (size_t)b * H * W;
        const float* R = rg + (size_t)b * H * W;
        float asum = 0.f, cl = 0.f, cr = 0.f;
        #pragma unroll
        for (int it = 0; it < 2; it++) {
            int t = lane + it * 32;
            if (t < NTAPS) {
                float ox = (float)(t % PATCH - HALF);
                float oy = (float)(t / PATCH - HALF);
                float vl = bilinear(L, klx + ox, kly + oy, W, H);
                float vr = bilinear(R, krx + ox, kry + oy, W, H);
                asum += fabsf(vl - vr);
                if (t == CENTER) { cl = vl; cr = vr; }
            }
        }
        #pragma unroll
        for (int o = 16; o > 0; o >>= 1)
            asum += __shfl_down_sync(0xffffffffu, asum, o);
        cl = __shfl_sync(0xffffffffu, cl, CENTER);
        cr = __shfl_sync(0xffffffffu, cr, CENTER);

        if (lane == 0) {
            float diffm = asum / 49.f;
            float isb   = (cl > 0.02f) ? 1.f : 0.f;
            float w     = sc * isb;
            float ydiff = fabsf(kly - kry);
            atomicAdd(&sacc[0], sc);
            atomicAdd(&sacc[1], ydiff * sc);
            atomicAdd(&sacc[2], ydiff);
            atomicAdd(&sacc[3], w);
            atomicAdd(&sacc[4], diffm * w);
            atomicAdd(&sacc[5], smooth_l1f(cl, cr, 1.f) * w);
            if (sc > 0.1f) atomicAdd(&scnt, 1);
            if (valid) {
                atomicAdd(&g_validn[b], 1);
                atomicAdd(&g_Sh[b], hh);
            }
        }
    }
    __syncthreads();
    if (tid < 6) atomicAdd(&g_acc[tid], sacc[tid]);
    if (tid == 6 && scnt) atomicAdd(&g_cnt, scnt);
}

// ---------------- kernel 2: 5-NN + smooth/slope terms ----------------
// one thread per point n; shared tiles over m; warp-uniform j (LDS broadcast)
__global__ void knn_kernel(int B, int N) {
    int b = blockIdx.y;
    int n = blockIdx.x * blockDim.x + threadIdx.x;
    int rowBase = b * N;

    bool active = false;
    float xn = 0.f, zn = 0.f, sqn = 0.f, hn = 0.f;
    if (n < N) {
        int p = rowBase + n;
        active = (g_valid[p] != 0);
        xn = g_x[p]; zn = g_z[p]; sqn = g_sq[p]; hn = g_h[p];
    }

    float d2k[KNN], hk[KNN];
    #pragma unroll
    for (int k = 0; k < KNN; k++) { d2k[k] = 3.4e38f; hk[k] = 0.f; }

    __shared__ float4 tile[256];
    for (int base = 0; base < N; base += 256) {
        int m = base + threadIdx.x;
        if (m < N) {
            int q = rowBase + m;
            tile[threadIdx.x] = make_float4(g_x[q], g_z[q], g_h[q], g_sq[q]);
        }
        __syncthreads();
        int cnt = min(256, N - base);
        if (active) {
            for (int j = 0; j < cnt; j++) {
                float4 t = tile[j];
                float d2 = sqn + t.w - 2.f * (xn * t.x + zn * t.y);
                int m2 = base + j;
                if (d2 < d2k[KNN - 1] && m2 != n) {
                    d2k[KNN - 1] = d2; hk[KNN - 1] = t.z;
                    #pragma unroll
                    for (int k = KNN - 1; k > 0; k--) {
                        if (d2k[k] < d2k[k - 1]) {
                            float td = d2k[k]; d2k[k] = d2k[k - 1]; d2k[k - 1] = td;
                            float th = hk[k];  hk[k]  = hk[k - 1];  hk[k - 1]  = th;
                        }
                    }
                }
            }
        }
        __syncthreads();
    }

    float ls = 0.f, pensum = 0.f;
    if (active) {
        float lm = (hk[0] + hk[1] + hk[2] + hk[3] + hk[4]) / 5.f;
        ls = smooth_l1f(hn, lm, 0.01f);
        #pragma unroll
        for (int k = 0; k < KNN; k++) {
            float nd = fmaxf(sqrtf(fmaxf(d2k[k], 1e-12f)), 0.001f);
            float s  = fabsf(hk[k] - hn) / nd;
            pensum  += fmaxf(s - 0.4f, 0.f);
        }
    }
    // warp reduce then shared-atomic then global
    #pragma unroll
    for (int o = 16; o > 0; o >>= 1) {
        ls     += __shfl_down_sync(0xffffffffu, ls, o);
        pensum += __shfl_down_sync(0xffffffffu, pensum, o);
    }
    __shared__ float sls, ssl;
    if (threadIdx.x == 0) { sls = 0.f; ssl = 0.f; }
    __syncthreads();
    if ((threadIdx.x & 31) == 0) {
        atomicAdd(&sls, ls);
        atomicAdd(&ssl, pensum);
    }
    __syncthreads();
    if (threadIdx.x == 0) {
        atomicAdd(&g_Sls[b], sls);
        atomicAdd(&g_Ssl[b], ssl);
    }
}

// ---------------- kernel 3: finalize ----------------
__global__ void final_kernel(float* __restrict__ out, int B, int N) {
    if (threadIdx.x != 0 || blockIdx.x != 0) return;

    float ws = g_acc[0];
    float l_epi = (ws > 0.0001f) ? (g_acc[1] / fmaxf(ws, 1e-12f))
                                 : (g_acc[2] / (float)(B * N));
    float wsum = g_acc[3];
    float safe = fmaxf(wsum, 1e-12f);
    float l_masked    = (wsum > 0.0001f) ? (g_acc[4] / safe) : 0.f;
    float l_intensity = (wsum > 0.0001f) ? (g_acc[5] / safe) : 0.f;
    float l_photo = l_masked + l_intensity;

    float sum_ok = 0.f, s_ls = 0.f, s_sl = 0.f, s_lz = 0.f;
    for (int b = 0; b < B; b++) {
        int nvi  = g_validn[b];
        float nv = (float)max(nvi, 1);
        float ok = (nvi >= 10) ? 1.f : 0.f;
        s_ls   += ok * (g_Sls[b] / nv);
        s_sl   += ok * (g_Ssl[b] / (nv * (float)KNN));
        s_lz   += ok * fabsf(g_Sh[b] / nv);
        sum_ok += ok;
    }
    float nb = fmaxf(sum_ok, 1.f);
    bool gate = (g_cnt >= 10) && (sum_ok > 0.f);

    out[0] = l_photo;
    out[1] = l_epi;
    out[2] = gate ? (s_ls / nb) : 0.f;
    out[3] = gate ? (s_sl / nb) : 0.f;
    out[4] = gate ? (s_lz / nb) : 0.f;
}

// ---------------- launch ----------------
extern "C" void kernel_launch(void* const* d_in, const int* in_sizes, int n_in,
                              void* d_out, int out_size) {
    const float* lg     = (const float*)d_in[0];
    const float* rg     = (const float*)d_in[1];
    const float* kpl    = (const float*)d_in[2];
    const float* kpr    = (const float*)d_in[3];
    const float* scores = (const float*)d_in[4];
    const float* Q      = (const float*)d_in[5];
    float* out = (float*)d_out;

    int B = in_sizes[5] / 16;          // Q is B*4*4
    int N = in_sizes[4] / B;           // scores is B*N
    int HW = in_sizes[0] / B;          // lg is B*1*H*W
    int H = 720, W = 1280;
    if (HW != H * W) {                 // fallback: assume 16:9-ish not needed; keep HW consistent
        // best effort: treat as W = 1280 rows of HW/1280 (dataset is fixed at 720x1280)
        W = 1280; H = HW / W;
    }
    int total = B * N;

    zero_kernel<<<1, 256>>>();

    int blocks1 = (total + 7) / 8;
    point_kernel<<<blocks1, 256>>>(lg, rg, kpl, kpr, scores, Q, B, N, H, W);

    dim3 g2((N + 255) / 256, B);
    knn_kernel<<<g2, 256>>>(B, N);

    final_kernel<<<1, 32>>>(out, B, N);
}

// round 2
// speedup vs baseline: 1.1109x; 1.1109x over previous
#include <cuda_runtime.h>
#include <cuda_bf16.h>
#include <math.h>

// ---------------- constants ----------------
#define PATCH   7
#define HALF    3
#define KNN     5
#define KK      6        // K+1, self included then dropped
#define MAXPTS  65536
#define MAXB    64

// ---------------- device scratch ----------------
__device__ float g_x[MAXPTS];
__device__ float g_z[MAXPTS];
__device__ float g_h[MAXPTS];
__device__ float g_sq[MAXPTS];
__device__ unsigned char g_valid[MAXPTS];

__device__ int   g_validn[MAXB];
__device__ float g_Sh[MAXB];
__device__ float g_Sls[MAXB];
__device__ float g_Ssl[MAXB];

// [0]=sum(sc) [1]=sum(ydiff*sc) [2]=sum(ydiff) [3]=sum(w) [4]=sum(diff*w) [5]=sum(sl1*w)
__device__ float g_acc[8];
__device__ int   g_cnt;

// ---------------- helpers ----------------
__device__ __forceinline__ float smooth_l1f(float x, float y, float beta) {
    float d = fabsf(x - y);
    return d < beta ? 0.5f * d * d / beta : d - 0.5f * beta;
}

// full reference-exact bilinear with clipping (slow path only)
__device__ __forceinline__ float bilinear_ref(const float* __restrict__ im,
                                              float x, float y, int W, int H) {
    x = fminf(fmaxf(x, 0.f), (float)(W - 1));
    y = fminf(fmaxf(y, 0.f), (float)(H - 1));
    float x0 = floorf(x), y0 = floorf(y);
    float fx = x - x0, fy = y - y0;
    int x0i = min(max((int)x0, 0), W - 1);
    int x1i = min(x0i + 1, W - 1);
    int y0i = min(max((int)y0, 0), H - 1);
    int y1i = min(y0i + 1, H - 1);
    float v00 = __ldg(im + (size_t)y0i * W + x0i);
    float v01 = __ldg(im + (size_t)y0i * W + x1i);
    float v10 = __ldg(im + (size_t)y1i * W + x0i);
    float v11 = __ldg(im + (size_t)y1i * W + x1i);
    float top = v00 * (1.f - fx) + v01 * fx;
    float bot = v10 * (1.f - fx) + v11 * fx;
    return top * (1.f - fy) + bot * fy;
}

// Warp-cooperative 7x7 patch sampler. Lane layout: r = lane>>2 (window row 0..7),
// cg = (lane&3)*2 (window cols cg, cg+1). Produces taps t0=(r,cg), t1=(r,cg+1);
// valid taps are r<7 and j<7. Fast path: 2 LDG/lane, separable bilinear via shuffles.
__device__ __forceinline__ void sample_pair(const float* __restrict__ im,
                                            float cx, float cy, int W, int H,
                                            int lane, float& t0, float& t1) {
    float fix = floorf(cx), fiy = floorf(cy);
    float fx = cx - fix, fy = cy - fiy;
    int ix = (int)fix, iy = (int)fiy;
    int r = lane >> 2, cg = (lane & 3) << 1;
    bool fast = (ix >= 3) && (ix + 4 <= W - 1) && (iy >= 3) && (iy + 4 <= H - 1);
    if (fast) {
        const float* rp = im + (size_t)(iy - 3 + r) * W + (ix - 3 + cg);
        float w0 = __ldg(rp);
        float w1 = __ldg(rp + 1);
        float w2 = __shfl_down_sync(0xffffffffu, w0, 1);   // next col pair's first pixel
        float ci0 = fmaf(fx, w1 - w0, w0);
        float ci1 = fmaf(fx, w2 - w1, w1);
        float cj0 = __shfl_down_sync(0xffffffffu, ci0, 4); // next row group
        float cj1 = __shfl_down_sync(0xffffffffu, ci1, 4);
        t0 = fmaf(fy, cj0 - ci0, ci0);
        t1 = fmaf(fy, cj1 - ci1, ci1);
    } else {
        // rare: border clipping engaged -> reference-exact per-tap path
        t0 = bilinear_ref(im, cx + (float)(cg - 3), cy + (float)(r - 3), W, H);
        t1 = bilinear_ref(im, cx + (float)(cg - 2), cy + (float)(r - 3), W, H);
    }
}

// ---------------- kernel 0: zero accumulators ----------------
__global__ void zero_kernel() {
    int t = threadIdx.x;
    if (t < 8)   g_acc[t] = 0.f;
    if (t == 8)  g_cnt = 0;
    if (t < MAXB) {
        g_validn[t] = 0;
        g_Sh[t] = 0.f;
        g_Sls[t] = 0.f;
        g_Ssl[t] = 0.f;
    }
}

// ---------------- kernel 1: per-point photo + geometry ----------------
__global__ void point_kernel(const float* __restrict__ lg,
                             const float* __restrict__ rg,
                             const float* __restrict__ kpl,
                             const float* __restrict__ kpr,
                             const float* __restrict__ scores,
                             const float* __restrict__ Q,
                             int B, int N, int H, int W) {
    __shared__ float sacc[6];
    __shared__ int   scnt;
    int tid  = threadIdx.x;
    int warp = tid >> 5;
    int lane = tid & 31;
    if (tid < 6) sacc[tid] = 0.f;
    if (tid == 6) scnt = 0;
    __syncthreads();

    int total = B * N;
    int p = blockIdx.x * 8 + warp;
    if (p < total) {
        int b = p / N;
        float klx = __ldg(kpl + 2 * p),  kly = __ldg(kpl + 2 * p + 1);
        float krx = __ldg(kpr + 2 * p),  kry = __ldg(kpr + 2 * p + 1);
        float sc  = __ldg(scores + p);

        // geometry (uniform across warp; lane 0 writes)
        const float* Qb = Q + (size_t)b * 16;
        float disp = klx - krx;
        float p0 = Qb[0]  * klx + Qb[1]  * kly + Qb[2]  * disp + Qb[3];
        float p1 = Qb[4]  * klx + Qb[5]  * kly + Qb[6]  * disp + Qb[7];
        float p2 = Qb[8]  * klx + Qb[9]  * kly + Qb[10] * disp + Qb[11];
        float p3 = Qb[12] * klx + Qb[13] * kly + Qb[14] * disp + Qb[15];
        float Wc = fmaxf(p3, 1e-6f);
        float X = p0 / Wc, Y = p1 / Wc, Z = p2 / Wc;
        bool  valid = (Z > 100.f) && (Z < 30000.f) && (sc > 0.1f);
        float pmx = X / 1000.f;
        float hh  = Y / 1000.f;
        float pmz = Z / 1000.f;
        float sq  = pmx * pmx + pmz * pmz;

        if (lane == 0) {
            g_h[p]     = hh;
            g_valid[p] = valid ? 1 : 0;
            if (valid) { g_x[p] = pmx; g_z[p] = pmz; g_sq[p] = sq; }
            else       { g_x[p] = 0.f; g_z[p] = 0.f; g_sq[p] = 4e18f; }
        }

        // patch sampling (warp-cooperative, separable fast path)
        const float* L = lg + (size_t)b * H * W;
        const float* R = rg + (size_t)b * H * W;
        float tl0, tl1, tr0, tr1;
        sample_pair(L, klx, kly, W, H, lane, tl0, tl1);
        sample_pair(R, krx, kry, W, H, lane, tr0, tr1);

        int r = lane >> 2;
        float a = 0.f;
        if (r < 7) {
            a = fabsf(tl0 - tr0);
            if ((lane & 3) < 3) a += fabsf(tl1 - tr1);
        }
        #pragma unroll
        for (int o = 16; o > 0; o >>= 1)
            a += __shfl_down_sync(0xffffffffu, a, o);

        // center tap (3,3): lane 13 (r=3, cg=2), t1 slot
        float cl = __shfl_sync(0xffffffffu, tl1, 13);
        float cr = __shfl_sync(0xffffffffu, tr1, 13);

        if (lane == 0) {
            float diffm = a / 49.f;
            float isb   = (cl > 0.02f) ? 1.f : 0.f;
            float w     = sc * isb;
            float ydiff = fabsf(kly - kry);
            atomicAdd(&sacc[0], sc);
            atomicAdd(&sacc[1], ydiff * sc);
            atomicAdd(&sacc[2], ydiff);
            atomicAdd(&sacc[3], w);
            atomicAdd(&sacc[4], diffm * w);
            atomicAdd(&sacc[5], smooth_l1f(cl, cr, 1.f) * w);
            if (sc > 0.1f) atomicAdd(&scnt, 1);
            if (valid) {
                atomicAdd(&g_validn[b], 1);
                atomicAdd(&g_Sh[b], hh);
            }
        }
    }
    __syncthreads();
    if (tid < 6) atomicAdd(&g_acc[tid], sacc[tid]);
    if (tid == 6 && scnt) atomicAdd(&g_cnt, scnt);
}

// ---------------- kernel 2: 6-NN (incl self) split-m + merge ----------------
// block = 512 threads: t in [0,256) and t+256 handle the same point n,
// scanning disjoint halves of the m range; merged at the end.
__global__ void knn_kernel(int B, int N) {
    __shared__ float4 tile[2][256];
    __shared__ float  lists[512][2 * KK];
    __shared__ float  sls, ssl;

    int b   = blockIdx.y;
    int tid = threadIdx.x;
    int t   = tid & 255;
    int hs  = tid >> 8;            // which m-half
    int n   = blockIdx.x * 256 + t;
    int rowBase = b * N;

    int Nh   = (N + 1) >> 1;
    int mBeg = hs ? Nh : 0;
    int mEnd = hs ? N  : Nh;
    int trips = (Nh + 255) >> 8;

    bool active = false;
    float xn = 0.f, zn = 0.f, sqn = 0.f, hn = 0.f;
    if (n < N) {
        int p = rowBase + n;
        active = (g_valid[p] != 0);
        xn = g_x[p]; zn = g_z[p]; sqn = g_sq[p]; hn = g_h[p];
    }

    float d2k[KK], hk[KK];
    #pragma unroll
    for (int k = 0; k < KK; k++) { d2k[k] = 3.4e38f; hk[k] = 0.f; }

    if (tid == 0) { sls = 0.f; ssl = 0.f; }

    for (int it = 0; it < trips; it++) {
        int base = mBeg + it * 256;
        int m = base + t;
        if (m < mEnd) {
            int q = rowBase + m;
            tile[hs][t] = make_float4(g_x[q], g_z[q], g_h[q], g_sq[q]);
        }
        __syncthreads();
        int cnt = min(256, mEnd - base);
        if (active && cnt > 0) {
            #pragma unroll 4
            for (int j = 0; j < cnt; j++) {
                float4 v = tile[hs][j];
                // EXACT same arithmetic as the validated R1 kernel
                float d2 = sqn + v.w - 2.f * (xn * v.x + zn * v.y);
                if (d2 < d2k[KK - 1]) {
                    d2k[KK - 1] = d2; hk[KK - 1] = v.z;
                    #pragma unroll
                    for (int k = KK - 1; k > 0; k--) {
                        if (d2k[k] < d2k[k - 1]) {
                            float td = d2k[k]; d2k[k] = d2k[k - 1]; d2k[k - 1] = td;
                            float th = hk[k];  hk[k]  = hk[k - 1];  hk[k - 1]  = th;
                        }
                    }
                }
            }
        }
        __syncthreads();
    }

    // publish lists, merge pairs in lower half
    #pragma unroll
    for (int k = 0; k < KK; k++) {
        lists[tid][k]      = d2k[k];
        lists[tid][KK + k] = hk[k];
    }
    __syncthreads();

    float ls = 0.f, pensum = 0.f;
    if (tid < 256 && active) {
        const float* pa = lists[tid];        // my (lower-half) sorted list
        const float* pb = lists[tid + 256];  // partner's sorted list
        float md[KK], mh[KK];
        int ia = 0, ib = 0;
        #pragma unroll
        for (int k = 0; k < KK; k++) {
            float da = pa[ia], db = pb[ib];
            bool ta = (da <= db);
            md[k] = ta ? da : db;
            mh[k] = ta ? pa[KK + ia] : pb[KK + ib];
            ia += ta ? 1 : 0;
            ib += ta ? 0 : 1;
        }
        // md[0] is self (d2 ~ 0); neighbors are md[1..5]
        float lm = (mh[1] + mh[2] + mh[3] + mh[4] + mh[5]) / 5.f;
        ls = smooth_l1f(hn, lm, 0.01f);
        #pragma unroll
        for (int k = 1; k < KK; k++) {
            float nd = fmaxf(sqrtf(fmaxf(md[k], 1e-12f)), 0.001f);
            float s  = fabsf(mh[k] - hn) / nd;
            pensum  += fmaxf(s - 0.4f, 0.f);
        }
    }
    #pragma unroll
    for (int o = 16; o > 0; o >>= 1) {
        ls     += __shfl_down_sync(0xffffffffu, ls, o);
        pensum += __shfl_down_sync(0xffffffffu, pensum, o);
    }
    if ((tid & 31) == 0) {
        atomicAdd(&sls, ls);
        atomicAdd(&ssl, pensum);
    }
    __syncthreads();
    if (tid == 0) {
        atomicAdd(&g_Sls[b], sls);
        atomicAdd(&g_Ssl[b], ssl);
    }
}

// ---------------- kernel 3: finalize (parallel over batches) ----------------
__global__ void final_kernel(float* __restrict__ out, int B, int N) {
    int t = threadIdx.x;   // 32 threads
    float s_ls = 0.f, s_sl = 0.f, s_lz = 0.f, s_ok = 0.f;
    for (int b = t; b < B; b += 32) {
        int nvi  = g_validn[b];
        float nv = (float)max(nvi, 1);
        float ok = (nvi >= 10) ? 1.f : 0.f;
        s_ls += ok * (g_Sls[b] / nv);
        s_sl += ok * (g_Ssl[b] / (nv * (float)KNN));
        s_lz += ok * fabsf(g_Sh[b] / nv);
        s_ok += ok;
    }
    #pragma unroll
    for (int o = 16; o > 0; o >>= 1) {
        s_ls += __shfl_down_sync(0xffffffffu, s_ls, o);
        s_sl += __shfl_down_sync(0xffffffffu, s_sl, o);
        s_lz += __shfl_down_sync(0xffffffffu, s_lz, o);
        s_ok += __shfl_down_sync(0xffffffffu, s_ok, o);
    }
    if (t == 0) {
        float ws = g_acc[0];
        float l_epi = (ws > 0.0001f) ? (g_acc[1] / fmaxf(ws, 1e-12f))
                                     : (g_acc[2] / (float)(B * N));
        float wsum = g_acc[3];
        float safe = fmaxf(wsum, 1e-12f);
        float l_masked    = (wsum > 0.0001f) ? (g_acc[4] / safe) : 0.f;
        float l_intensity = (wsum > 0.0001f) ? (g_acc[5] / safe) : 0.f;

        float nb = fmaxf(s_ok, 1.f);
        bool gate = (g_cnt >= 10) && (s_ok > 0.f);

        out[0] = l_masked + l_intensity;
        out[1] = l_epi;
        out[2] = gate ? (s_ls / nb) : 0.f;
        out[3] = gate ? (s_sl / nb) : 0.f;
        out[4] = gate ? (s_lz / nb) : 0.f;
    }
}

// ---------------- launch ----------------
extern "C" void kernel_launch(void* const* d_in, const int* in_sizes, int n_in,
                              void* d_out, int out_size) {
    const float* lg     = (const float*)d_in[0];
    const float* rg     = (const float*)d_in[1];
    const float* kpl    = (const float*)d_in[2];
    const float* kpr    = (const float*)d_in[3];
    const float* scores = (const float*)d_in[4];
    const float* Q      = (const float*)d_in[5];
    float* out = (float*)d_out;

    int B = in_sizes[5] / 16;
    int N = in_sizes[4] / B;
    int HW = in_sizes[0] / B;
    int W = 1280, H = HW / W;
    if (H * W != HW) { W = 1280; H = HW / W; }
    int total = B * N;

    zero_kernel<<<1, 256>>>();

    int blocks1 = (total + 7) / 8;
    point_kernel<<<blocks1, 256>>>(lg, rg, kpl, kpr, scores, Q, B, N, H, W);

    dim3 g2((N + 255) / 256, B);
    knn_kernel<<<g2, 512>>>(B, N);

    final_kernel<<<1, 32>>>(out, B, N);
}